// round 4
// baseline (speedup 1.0000x reference)
#include <cuda_runtime.h>
#include <cstdint>

#define IND       1024
#define ODIM      128
#define BATCHN    65536
#define BM        128
#define KC        32                  // fp32 elems per K-chunk
#define NITER     (IND / KC)          // 32
#define NS        3
#define NTHR      512

#define PITCH     144                 // bytes per smem row (conflict-free, no swizzle)
#define PITCHF    36                  // floats per row
#define PANEL_F   (BM * PITCHF)       // 4608 floats per W k-panel

#define SM_MBAR     0                 // 3 mbarriers
#define SM_COEF     256               // a0[128], a1[128], bias[128]
#define SM_STAGE    2048
#define TILE_BYTES  (BM * PITCH)      // 18432
#define TO_X        0
#define TO_Y        (1 * TILE_BYTES)
#define TO_W0       (2 * TILE_BYTES)
#define TO_W1       (3 * TILE_BYTES)
#define STAGE_BYTES (4 * TILE_BYTES)  // 73728
#define STAGE_TX    (128 * 128 * 2 + 2 * TILE_BYTES)   // 69632 bytes per stage
#define SMEM_TOTAL  (SM_STAGE + NS * STAGE_BYTES)      // 223232
#define EXP         132               // exchange pitch (floats)

typedef uint32_t U32;

// W pre-packed: [kchunk][row][36 floats] (cols 32..35 are zero pad)
__device__ float g_W0p[NITER * PANEL_F];
__device__ float g_W1p[NITER * PANEL_F];

// ---------------- PTX helpers ----------------

static __device__ __forceinline__ U32 s2u(const void* p) {
    U32 a;
    asm("{ .reg .u64 t; cvta.to.shared.u64 t, %1; cvt.u32.u64 %0, t; }" : "=r"(a) : "l"(p));
    return a;
}

static __device__ __forceinline__ void bulk_g2s(U32 dst, const void* src, U32 bytes, U32 mbar) {
    asm volatile("cp.async.bulk.shared::cluster.global.mbarrier::complete_tx::bytes "
                 "[%0], [%1], %2, [%3];"
                 :: "r"(dst), "l"(src), "r"(bytes), "r"(mbar) : "memory");
}

static __device__ __forceinline__ void mbar_init(U32 a, U32 cnt) {
    asm volatile("mbarrier.init.shared.b64 [%0], %1;" :: "r"(a), "r"(cnt) : "memory");
}
static __device__ __forceinline__ void mbar_expect(U32 a, U32 tx) {
    asm volatile("mbarrier.arrive.expect_tx.shared.b64 _, [%0], %1;" :: "r"(a), "r"(tx) : "memory");
}

#define MBAR_WAIT(addr, par) do {                                              \
    asm volatile("{\n\t.reg .pred P1;\n\t"                                     \
        "LAB_W_%=:\n\t"                                                        \
        "mbarrier.try_wait.parity.shared::cta.b64 P1, [%0], %1;\n\t"           \
        "@P1 bra.uni LAB_D_%=;\n\t"                                            \
        "bra.uni LAB_W_%=;\n\t"                                                \
        "LAB_D_%=:\n\t}"                                                       \
        :: "r"(addr), "r"(par) : "memory");                                    \
} while (0)

#define FENCE_PROXY() asm volatile("fence.proxy.async.shared::cta;" ::: "memory")

static __device__ __forceinline__ void ldsm4(U32& r0, U32& r1, U32& r2, U32& r3, U32 addr) {
    asm volatile("ldmatrix.sync.aligned.m8n8.x4.shared.b16 {%0,%1,%2,%3}, [%4];"
                 : "=r"(r0), "=r"(r1), "=r"(r2), "=r"(r3) : "r"(addr));
}

static __device__ __forceinline__ void mma8(float* c, U32 a0, U32 a1, U32 a2, U32 a3,
                                            U32 b0, U32 b1) {
    asm volatile("mma.sync.aligned.m16n8k8.row.col.f32.tf32.tf32.f32 "
                 "{%0,%1,%2,%3}, {%4,%5,%6,%7}, {%8,%9}, {%0,%1,%2,%3};"
                 : "+f"(c[0]), "+f"(c[1]), "+f"(c[2]), "+f"(c[3])
                 : "r"(a0), "r"(a1), "r"(a2), "r"(a3), "r"(b0), "r"(b1));
}

// ---------------- weight normalization + k-panel packing ----------------
// w' = (w - mean(w)) * rsqrt(sum((w-mean)^2)), written as [kchunk][row][36] panels
__global__ void normalize_kernel(const float* __restrict__ w) {
    int row  = blockIdx.x & (ODIM - 1);
    int half = blockIdx.x >> 7;
    const float* src = w + (size_t)row * (2 * IND) + (size_t)half * IND;
    float* dst = half ? g_W1p : g_W0p;
    int t = threadIdx.x;  // 256 threads
    float v[4], s = 0.f, s2 = 0.f;
#pragma unroll
    for (int i = 0; i < 4; ++i) { v[i] = src[t + 256 * i]; s += v[i]; s2 += v[i] * v[i]; }
#pragma unroll
    for (int o = 16; o; o >>= 1) {
        s  += __shfl_xor_sync(~0u, s,  o);
        s2 += __shfl_xor_sync(~0u, s2, o);
    }
    __shared__ float sh[18];
    if ((t & 31) == 0) { sh[t >> 5] = s; sh[8 + (t >> 5)] = s2; }
    __syncthreads();
    if (t == 0) {
        float S = 0.f, S2 = 0.f;
#pragma unroll
        for (int i = 0; i < 8; ++i) { S += sh[i]; S2 += sh[8 + i]; }
        float mu = S * (1.f / IND);
        float ss = S2 - (float)IND * mu * mu;
        sh[16] = mu; sh[17] = rsqrtf(ss);
    }
    __syncthreads();
    float mu = sh[16], inv = sh[17];
#pragma unroll
    for (int i = 0; i < 4; ++i) {
        int k  = t + 256 * i;
        int kc = k >> 5, wv = k & 31;
        dst[(size_t)kc * PANEL_F + row * PITCHF + wv] = (v[i] - mu) * inv;
    }
    // zero the pad columns (32..35) for this row across all panels
    if (t < 128) {
        int kc = t >> 2, wv = 32 + (t & 3);
        dst[(size_t)kc * PANEL_F + row * PITCHF + wv] = 0.f;
    }
}

// ---------------- main fused GEMM ----------------
// 16 warps: warps 0-7: out0 = x*W0^T, warps 8-15: out1 = y*W1^T.
// Per-GEMM warp grid 4(m) x 2(n): warp tile 32x64.

static __device__ __forceinline__ void load_stage(U32 sb, int slot, int kchunk,
                                                  const float* x, const float* y, int m0) {
    const int tid = threadIdx.x;
    if (tid >= 258) return;
    const U32 st = sb + SM_STAGE + slot * STAGE_BYTES;
    const U32 mb = sb + SM_MBAR + slot * 8;
    FENCE_PROXY();
    if (tid == 0) mbar_expect(mb, STAGE_TX);
    if (tid < 256) {
        const int r = tid & 127;
        const float* src = (tid < 128 ? x : y) + (size_t)(m0 + r) * IND + kchunk * KC;
        const U32 dst = st + (tid < 128 ? TO_X : TO_Y) + (U32)(r * PITCH);
        bulk_g2s(dst, src, 128, mb);
    } else if (tid == 256) {
        bulk_g2s(st + TO_W0, g_W0p + (size_t)kchunk * PANEL_F, TILE_BYTES, mb);
    } else {
        bulk_g2s(st + TO_W1, g_W1p + (size_t)kchunk * PANEL_F, TILE_BYTES, mb);
    }
}

__global__ void __launch_bounds__(NTHR, 1)
gemm_kernel(const float* __restrict__ x, const float* __restrict__ y,
            const float* __restrict__ fc_bias, const float* __restrict__ a0,
            const float* __restrict__ a1, float* __restrict__ out) {
    extern __shared__ char smem[];
    const U32 sb = s2u(smem);
    const int tid = threadIdx.x;
    const int wid = tid >> 5, lid = tid & 31;
    const int m0 = blockIdx.x * BM;

    if (tid == 0) {
#pragma unroll
        for (int s = 0; s < NS; ++s) mbar_init(sb + SM_MBAR + s * 8, 1);
    }
    if (tid < 128) {
        float* sc = (float*)(smem + SM_COEF);
        sc[tid] = a0[tid]; sc[128 + tid] = a1[tid]; sc[256 + tid] = fc_bias[tid];
    }
    __syncthreads();

    // prologue: fill all NS stages
#pragma unroll
    for (int s = 0; s < NS; ++s) load_stage(sb, s, s, x, y, m0);

    // warp role
    const int g1 = wid >> 3;             // 0: GEMM0 (x,W0), 1: GEMM1 (y,W1)
    const int wl = wid & 7;
    const int mw = wl & 3;               // m-quarter (32 rows)
    const int nw = wl >> 2;              // n-half (64 cols)

    const int sel  = lid >> 3;
    const int lrow = lid & 7;
    const int aRowL = (sel & 1) * 8 + lrow;
    const U32 aKb   = (U32)((sel >> 1) * 16);
    const int bRowL = sel * 8 + lrow;

    U32 aOff[2];
#pragma unroll
    for (int mt = 0; mt < 2; ++mt)
        aOff[mt] = (U32)((mw * 32 + mt * 16 + aRowL) * PITCH) + aKb;
    U32 bOff[2];
#pragma unroll
    for (int g = 0; g < 2; ++g)
        bOff[g] = (U32)((nw * 64 + g * 32 + bRowL) * PITCH);

    float acc[2][8][4];
#pragma unroll
    for (int mt = 0; mt < 2; ++mt)
#pragma unroll
        for (int nt = 0; nt < 8; ++nt)
#pragma unroll
            for (int q = 0; q < 4; ++q) acc[mt][nt][q] = 0.f;

    const U32 toA = g1 ? TO_Y : TO_X;
    const U32 toB = g1 ? TO_W1 : TO_W0;

    int phase0 = 0, phase1 = 0, phase2 = 0;
    for (int i = 0; i < NITER; ++i) {
        const int slot = i % NS;
        int ph = (slot == 0) ? phase0 : (slot == 1) ? phase1 : phase2;
        MBAR_WAIT(sb + SM_MBAR + slot * 8, (U32)ph);
        if (slot == 0) phase0 ^= 1; else if (slot == 1) phase1 ^= 1; else phase2 ^= 1;

        const U32 st = sb + SM_STAGE + (U32)(slot * STAGE_BYTES);
        const U32 abase = st + toA;
        const U32 bbase = st + toB;
#pragma unroll
        for (int ks = 0; ks < 4; ++ks) {       // 4 k8-steps per 32-float chunk
            const U32 kb = (U32)(ks * 32);
            U32 a[2][4];
#pragma unroll
            for (int mt = 0; mt < 2; ++mt)
                ldsm4(a[mt][0], a[mt][1], a[mt][2], a[mt][3], abase + aOff[mt] + kb);
            U32 b0[8], b1[8];
#pragma unroll
            for (int g = 0; g < 2; ++g) {
                ldsm4(b0[4 * g + 0], b0[4 * g + 1], b0[4 * g + 2], b0[4 * g + 3],
                      bbase + bOff[g] + kb);
                ldsm4(b1[4 * g + 0], b1[4 * g + 1], b1[4 * g + 2], b1[4 * g + 3],
                      bbase + bOff[g] + kb + 16u);
            }
#pragma unroll
            for (int mt = 0; mt < 2; ++mt)
#pragma unroll
                for (int nt = 0; nt < 8; ++nt)
                    mma8(acc[mt][nt], a[mt][0], a[mt][1], a[mt][2], a[mt][3],
                         b0[nt], b1[nt]);
        }
        __syncthreads();                       // all warps done reading slot
        if (i + NS < NITER) load_stage(sb, slot, i + NS, x, y, m0);
    }

    // ---------- epilogue ----------
    float* exch = (float*)(smem + SM_STAGE);   // reuse stage area: 128 x EXP fp32
    const float* sa0 = (const float*)(smem + SM_COEF);
    const float* sa1 = sa0 + 128;
    const float* sbs = sa0 + 256;

    const int rowb = mw * 32 + (lid >> 2);
    const int colb = nw * 64 + 2 * (lid & 3);

    if (!g1) {
#pragma unroll
        for (int mt = 0; mt < 2; ++mt) {
            const int rl = rowb + mt * 16;
#pragma unroll
            for (int nt = 0; nt < 8; ++nt) {
                const int c = colb + nt * 8;
                float2 v0 = make_float2(acc[mt][nt][0], acc[mt][nt][1]);
                float2 v1 = make_float2(acc[mt][nt][2], acc[mt][nt][3]);
                *(float2*)(out + (size_t)(m0 + rl)     * ODIM + c) = v0;
                *(float2*)(out + (size_t)(m0 + rl + 8) * ODIM + c) = v1;
                *(float2*)(exch + rl * EXP + c)       = v0;
                *(float2*)(exch + (rl + 8) * EXP + c) = v1;
            }
        }
    } else {
        float* o1 = out + (size_t)BATCHN * ODIM;
#pragma unroll
        for (int mt = 0; mt < 2; ++mt) {
            const int rl = rowb + mt * 16;
#pragma unroll
            for (int nt = 0; nt < 8; ++nt) {
                const int c = colb + nt * 8;
                *(float2*)(o1 + (size_t)(m0 + rl)     * ODIM + c) =
                    make_float2(acc[mt][nt][0], acc[mt][nt][1]);
                *(float2*)(o1 + (size_t)(m0 + rl + 8) * ODIM + c) =
                    make_float2(acc[mt][nt][2], acc[mt][nt][3]);
            }
        }
    }
    __syncthreads();

    if (g1) {
        float* o2 = out + 2 * (size_t)BATCHN * ODIM;
#pragma unroll
        for (int mt = 0; mt < 2; ++mt) {
            const int rl = rowb + mt * 16;
#pragma unroll
            for (int nt = 0; nt < 8; ++nt) {
                const int c = colb + nt * 8;
                float2 p0 = *(const float2*)(exch + rl * EXP + c);
                float2 p1 = *(const float2*)(exch + (rl + 8) * EXP + c);
                const float A0x = sa0[c], A0y = sa0[c + 1];
                const float A1x = sa1[c], A1y = sa1[c + 1];
                const float Bx  = sbs[c], By  = sbs[c + 1];
                float2 r0, r1;
                r0.x = p0.x * A0x + acc[mt][nt][0] * A1x + Bx;
                r0.y = p0.y * A0y + acc[mt][nt][1] * A1y + By;
                r1.x = p1.x * A0x + acc[mt][nt][2] * A1x + Bx;
                r1.y = p1.y * A0y + acc[mt][nt][3] * A1y + By;
                *(float2*)(o2 + (size_t)(m0 + rl)     * ODIM + c) = r0;
                *(float2*)(o2 + (size_t)(m0 + rl + 8) * ODIM + c) = r1;
            }
        }
    }
}

// ---------------- launch ----------------

extern "C" void kernel_launch(void* const* d_in, const int* in_sizes, int n_in,
                              void* d_out, int out_size) {
    const float* x  = (const float*)d_in[0];
    const float* y  = (const float*)d_in[1];
    const float* fw = (const float*)d_in[2];
    const float* fb = (const float*)d_in[3];
    const float* a0 = (const float*)d_in[4];
    const float* a1 = (const float*)d_in[5];
    float* out = (float*)d_out;

    normalize_kernel<<<2 * ODIM, 256>>>(fw);

    cudaFuncSetAttribute(gemm_kernel, cudaFuncAttributeMaxDynamicSharedMemorySize, SMEM_TOTAL);
    gemm_kernel<<<BATCHN / BM, NTHR, SMEM_TOTAL>>>(x, y, fb, a0, a1, out);
}

// round 5
// speedup vs baseline: 1.1497x; 1.1497x over previous
#include <cuda_runtime.h>
#include <cstdint>

#define IND       1024
#define ODIM      128
#define BATCHN    65536
#define BM        128
#define KC        32                  // fp32 elems per K-chunk (128B row)
#define NITER     (IND / KC)          // 32
#define NS        3
#define NTHR      512

#define PANEL_F   (BM * KC)           // 4096 floats per W k-panel (16KB)

#define SM_MBAR     0                 // 3 mbarriers (W TMA completion)
#define SM_COEF     256               // a0[128], a1[128], bias[128]
#define SM_STAGE    2048
#define TILE_BYTES  16384             // 128 rows x 128B
#define TO_X        0
#define TO_Y        (1 * TILE_BYTES)
#define TO_W0       (2 * TILE_BYTES)
#define TO_W1       (3 * TILE_BYTES)
#define STAGE_BYTES (4 * TILE_BYTES)  // 65536
#define W_TX        (2 * TILE_BYTES)  // expect_tx per stage (W0+W1)
#define SMEM_TOTAL  (SM_STAGE + NS * STAGE_BYTES)   // 198656
#define EXP         132               // exchange pitch (floats)

typedef uint32_t U32;

// W pre-packed per k-chunk, swizzle PRE-APPLIED so a linear bulk copy lands
// in smem with the exact layout R3's swizzled cp16 produced.
__device__ float g_W0p[NITER * PANEL_F];
__device__ float g_W1p[NITER * PANEL_F];

// ---------------- PTX helpers ----------------

static __device__ __forceinline__ U32 s2u(const void* p) {
    U32 a;
    asm("{ .reg .u64 t; cvta.to.shared.u64 t, %1; cvt.u32.u64 %0, t; }" : "=r"(a) : "l"(p));
    return a;
}

static __device__ __forceinline__ void cp16(U32 dst, const void* src) {
    asm volatile("cp.async.cg.shared.global [%0], [%1], 16;" :: "r"(dst), "l"(src));
}
static __device__ __forceinline__ void cp_commit() {
    asm volatile("cp.async.commit_group;" ::: "memory");
}
template <int N> static __device__ __forceinline__ void cp_wait() {
    asm volatile("cp.async.wait_group %0;" :: "n"(N) : "memory");
}

static __device__ __forceinline__ void bulk_g2s(U32 dst, const void* src, U32 bytes, U32 mbar) {
    asm volatile("cp.async.bulk.shared::cluster.global.mbarrier::complete_tx::bytes "
                 "[%0], [%1], %2, [%3];"
                 :: "r"(dst), "l"(src), "r"(bytes), "r"(mbar) : "memory");
}

static __device__ __forceinline__ void mbar_init(U32 a, U32 cnt) {
    asm volatile("mbarrier.init.shared.b64 [%0], %1;" :: "r"(a), "r"(cnt) : "memory");
}
static __device__ __forceinline__ void mbar_expect(U32 a, U32 tx) {
    asm volatile("mbarrier.arrive.expect_tx.shared.b64 _, [%0], %1;" :: "r"(a), "r"(tx) : "memory");
}

#define MBAR_WAIT(addr, par) do {                                              \
    asm volatile("{\n\t.reg .pred P1;\n\t"                                     \
        "LAB_W_%=:\n\t"                                                        \
        "mbarrier.try_wait.parity.shared::cta.b64 P1, [%0], %1;\n\t"           \
        "@P1 bra.uni LAB_D_%=;\n\t"                                            \
        "bra.uni LAB_W_%=;\n\t"                                                \
        "LAB_D_%=:\n\t}"                                                       \
        :: "r"(addr), "r"(par) : "memory");                                    \
} while (0)

#define FENCE_PROXY() asm volatile("fence.proxy.async.shared::cta;" ::: "memory")

static __device__ __forceinline__ void ldsm4(U32& r0, U32& r1, U32& r2, U32& r3, U32 addr) {
    asm volatile("ldmatrix.sync.aligned.m8n8.x4.shared.b16 {%0,%1,%2,%3}, [%4];"
                 : "=r"(r0), "=r"(r1), "=r"(r2), "=r"(r3) : "r"(addr));
}

static __device__ __forceinline__ void mma8(float* c, U32 a0, U32 a1, U32 a2, U32 a3,
                                            U32 b0, U32 b1) {
    asm volatile("mma.sync.aligned.m16n8k8.row.col.f32.tf32.tf32.f32 "
                 "{%0,%1,%2,%3}, {%4,%5,%6,%7}, {%8,%9}, {%0,%1,%2,%3};"
                 : "+f"(c[0]), "+f"(c[1]), "+f"(c[2]), "+f"(c[3])
                 : "r"(a0), "r"(a1), "r"(a2), "r"(a3), "r"(b0), "r"(b1));
}

// ---------------- weight normalization + swizzled k-panel packing ----------------
// w' = (w - mean(w)) * rsqrt(sum((w-mean)^2))
// dst panel layout: [kchunk][row][col ^ ((row&7)<<2)] (float units)
__global__ void normalize_kernel(const float* __restrict__ w) {
    int row  = blockIdx.x & (ODIM - 1);
    int half = blockIdx.x >> 7;
    const float* src = w + (size_t)row * (2 * IND) + (size_t)half * IND;
    float* dst = half ? g_W1p : g_W0p;
    int t = threadIdx.x;  // 256 threads
    float v[4], s = 0.f, s2 = 0.f;
#pragma unroll
    for (int i = 0; i < 4; ++i) { v[i] = src[t + 256 * i]; s += v[i]; s2 += v[i] * v[i]; }
#pragma unroll
    for (int o = 16; o; o >>= 1) {
        s  += __shfl_xor_sync(~0u, s,  o);
        s2 += __shfl_xor_sync(~0u, s2, o);
    }
    __shared__ float sh[18];
    if ((t & 31) == 0) { sh[t >> 5] = s; sh[8 + (t >> 5)] = s2; }
    __syncthreads();
    if (t == 0) {
        float S = 0.f, S2 = 0.f;
#pragma unroll
        for (int i = 0; i < 8; ++i) { S += sh[i]; S2 += sh[8 + i]; }
        float mu = S * (1.f / IND);
        float ss = S2 - (float)IND * mu * mu;
        sh[16] = mu; sh[17] = rsqrtf(ss);
    }
    __syncthreads();
    float mu = sh[16], inv = sh[17];
#pragma unroll
    for (int i = 0; i < 4; ++i) {
        int k   = t + 256 * i;
        int kc  = k >> 5, col = k & 31;
        int sc  = col ^ ((row & 7) << 2);       // pre-applied 128B swizzle (float units)
        dst[(size_t)kc * PANEL_F + row * KC + sc] = (v[i] - mu) * inv;
    }
}

// ---------------- main fused GEMM ----------------
// 16 warps: warps 0-7: out0 = x*W0^T, warps 8-15: out1 = y*W1^T.
// Per-GEMM warp grid 4(m) x 2(n): warp tile 32x64.

static __device__ __forceinline__ void load_stage(U32 sb, int slot, int kchunk,
                                                  const float* x, const float* y, int m0) {
    const int tid = threadIdx.x;
    const U32 st = sb + SM_STAGE + slot * STAGE_BYTES;
    // x/y via cp.async: 2048 x 16B per stage, 4 per thread
    const int ch = tid & 7;          // 16B chunk within 128B row
    const int r0 = tid >> 3;         // base row 0..63
    const int kofs = kchunk * KC + ch * 4;
    const float* px = x + (size_t)(m0 + r0) * IND + kofs;
    const float* py = y + (size_t)(m0 + r0) * IND + kofs;
#pragma unroll
    for (int p = 0; p < 2; ++p) {
        const int row = r0 + 64 * p;
        const U32 c  = (U32)(ch * 16);
        const U32 so = (U32)(row * 128) + (c ^ (U32)((row & 7) << 4));
        cp16(st + TO_X + so, px + (size_t)(64 * p) * IND);
        cp16(st + TO_Y + so, py + (size_t)(64 * p) * IND);
    }
    // W via two 16KB bulk copies (pre-swizzled panels)
    if (tid == 0) {
        const U32 mb = sb + SM_MBAR + slot * 8;
        FENCE_PROXY();
        mbar_expect(mb, W_TX);
        bulk_g2s(st + TO_W0, g_W0p + (size_t)kchunk * PANEL_F, TILE_BYTES, mb);
        bulk_g2s(st + TO_W1, g_W1p + (size_t)kchunk * PANEL_F, TILE_BYTES, mb);
    }
}

__global__ void __launch_bounds__(NTHR, 1)
gemm_kernel(const float* __restrict__ x, const float* __restrict__ y,
            const float* __restrict__ fc_bias, const float* __restrict__ a0,
            const float* __restrict__ a1, float* __restrict__ out) {
    extern __shared__ char smem[];
    const U32 sb = s2u(smem);
    const int tid = threadIdx.x;
    const int wid = tid >> 5, lid = tid & 31;
    const int m0 = blockIdx.x * BM;

    if (tid == 0) {
#pragma unroll
        for (int s = 0; s < NS; ++s) mbar_init(sb + SM_MBAR + s * 8, 1);
    }
    if (tid < 128) {
        float* sc = (float*)(smem + SM_COEF);
        sc[tid] = a0[tid]; sc[128 + tid] = a1[tid]; sc[256 + tid] = fc_bias[tid];
    }
    __syncthreads();   // mbarriers initialized before any TMA

    // prologue: fill all NS stages
#pragma unroll
    for (int s = 0; s < NS; ++s) { load_stage(sb, s, s, x, y, m0); cp_commit(); }

    // warp role
    const int g1 = wid >> 3;             // 0: GEMM0 (x,W0), 1: GEMM1 (y,W1)
    const int wl = wid & 7;
    const int mw = wl & 3;               // m-quarter (32 rows)
    const int nw = wl >> 2;              // n-half (64 cols)

    const int sel  = lid >> 3;
    const int lrow = lid & 7;
    const int aRowL = (sel & 1) * 8 + lrow;
    const U32 aKb   = (U32)((sel >> 1) * 16);
    const int bRowL = sel * 8 + lrow;

    U32 aRowOff[2], aXor[2];
#pragma unroll
    for (int mt = 0; mt < 2; ++mt) {
        int r = mw * 32 + mt * 16 + aRowL;
        aRowOff[mt] = (U32)(r * 128);
        aXor[mt]    = (U32)((r & 7) << 4);
    }
    U32 bRowOff[2], bXor[2];
#pragma unroll
    for (int g = 0; g < 2; ++g) {
        int r = nw * 64 + g * 32 + bRowL;
        bRowOff[g] = (U32)(r * 128);
        bXor[g]    = (U32)((r & 7) << 4);
    }

    float acc[2][8][4];
#pragma unroll
    for (int mt = 0; mt < 2; ++mt)
#pragma unroll
        for (int nt = 0; nt < 8; ++nt)
#pragma unroll
            for (int q = 0; q < 4; ++q) acc[mt][nt][q] = 0.f;

    const U32 toA = g1 ? TO_Y : TO_X;
    const U32 toB = g1 ? TO_W1 : TO_W0;

    int phase0 = 0, phase1 = 0, phase2 = 0;
    for (int i = 0; i < NITER; ++i) {
        const int slot = i % NS;
        int ph = (slot == 0) ? phase0 : (slot == 1) ? phase1 : phase2;
        MBAR_WAIT(sb + SM_MBAR + slot * 8, (U32)ph);     // W ready
        if (slot == 0) phase0 ^= 1; else if (slot == 1) phase1 ^= 1; else phase2 ^= 1;
        cp_wait<NS - 1>();                               // x/y ready
        __syncthreads();

        const U32 st = sb + SM_STAGE + (U32)(slot * STAGE_BYTES);
        const U32 abase = st + toA;
        const U32 bbase = st + toB;
#pragma unroll
        for (int ks = 0; ks < 4; ++ks) {       // 4 k8-steps per 32-float chunk
            const U32 kb = (U32)(ks * 32);
            U32 a[2][4];
#pragma unroll
            for (int mt = 0; mt < 2; ++mt)
                ldsm4(a[mt][0], a[mt][1], a[mt][2], a[mt][3],
                      abase + aRowOff[mt] + ((kb + aKb) ^ aXor[mt]));
            U32 b0[8], b1[8];
#pragma unroll
            for (int g = 0; g < 2; ++g) {
                ldsm4(b0[4 * g + 0], b0[4 * g + 1], b0[4 * g + 2], b0[4 * g + 3],
                      bbase + bRowOff[g] + ((kb + 0u)  ^ bXor[g]));
                ldsm4(b1[4 * g + 0], b1[4 * g + 1], b1[4 * g + 2], b1[4 * g + 3],
                      bbase + bRowOff[g] + ((kb + 16u) ^ bXor[g]));
            }
#pragma unroll
            for (int mt = 0; mt < 2; ++mt)
#pragma unroll
                for (int nt = 0; nt < 8; ++nt)
                    mma8(acc[mt][nt], a[mt][0], a[mt][1], a[mt][2], a[mt][3],
                         b0[nt], b1[nt]);
        }
        __syncthreads();                       // all warps done reading slot
        if (i + NS < NITER) load_stage(sb, slot, i + NS, x, y, m0);
        cp_commit();
    }
    __syncthreads();

    // ---------- epilogue ----------
    float* exch = (float*)(smem + SM_STAGE);   // reuse stage area: 128 x EXP fp32
    const float* sa0 = (const float*)(smem + SM_COEF);
    const float* sa1 = sa0 + 128;
    const float* sbs = sa0 + 256;

    const int rowb = mw * 32 + (lid >> 2);
    const int colb = nw * 64 + 2 * (lid & 3);

    if (!g1) {
#pragma unroll
        for (int mt = 0; mt < 2; ++mt) {
            const int rl = rowb + mt * 16;
#pragma unroll
            for (int nt = 0; nt < 8; ++nt) {
                const int c = colb + nt * 8;
                float2 v0 = make_float2(acc[mt][nt][0], acc[mt][nt][1]);
                float2 v1 = make_float2(acc[mt][nt][2], acc[mt][nt][3]);
                *(float2*)(out + (size_t)(m0 + rl)     * ODIM + c) = v0;
                *(float2*)(out + (size_t)(m0 + rl + 8) * ODIM + c) = v1;
                *(float2*)(exch + rl * EXP + c)       = v0;
                *(float2*)(exch + (rl + 8) * EXP + c) = v1;
            }
        }
    } else {
        float* o1 = out + (size_t)BATCHN * ODIM;
#pragma unroll
        for (int mt = 0; mt < 2; ++mt) {
            const int rl = rowb + mt * 16;
#pragma unroll
            for (int nt = 0; nt < 8; ++nt) {
                const int c = colb + nt * 8;
                *(float2*)(o1 + (size_t)(m0 + rl)     * ODIM + c) =
                    make_float2(acc[mt][nt][0], acc[mt][nt][1]);
                *(float2*)(o1 + (size_t)(m0 + rl + 8) * ODIM + c) =
                    make_float2(acc[mt][nt][2], acc[mt][nt][3]);
            }
        }
    }
    __syncthreads();

    if (g1) {
        float* o2 = out + 2 * (size_t)BATCHN * ODIM;
#pragma unroll
        for (int mt = 0; mt < 2; ++mt) {
            const int rl = rowb + mt * 16;
#pragma unroll
            for (int nt = 0; nt < 8; ++nt) {
                const int c = colb + nt * 8;
                float2 p0 = *(const float2*)(exch + rl * EXP + c);
                float2 p1 = *(const float2*)(exch + (rl + 8) * EXP + c);
                const float A0x = sa0[c], A0y = sa0[c + 1];
                const float A1x = sa1[c], A1y = sa1[c + 1];
                const float Bx  = sbs[c], By  = sbs[c + 1];
                float2 r0, r1;
                r0.x = p0.x * A0x + acc[mt][nt][0] * A1x + Bx;
                r0.y = p0.y * A0y + acc[mt][nt][1] * A1y + By;
                r1.x = p1.x * A0x + acc[mt][nt][2] * A1x + Bx;
                r1.y = p1.y * A0y + acc[mt][nt][3] * A1y + By;
                *(float2*)(o2 + (size_t)(m0 + rl)     * ODIM + c) = r0;
                *(float2*)(o2 + (size_t)(m0 + rl + 8) * ODIM + c) = r1;
            }
        }
    }
}

// ---------------- launch ----------------

extern "C" void kernel_launch(void* const* d_in, const int* in_sizes, int n_in,
                              void* d_out, int out_size) {
    const float* x  = (const float*)d_in[0];
    const float* y  = (const float*)d_in[1];
    const float* fw = (const float*)d_in[2];
    const float* fb = (const float*)d_in[3];
    const float* a0 = (const float*)d_in[4];
    const float* a1 = (const float*)d_in[5];
    float* out = (float*)d_out;

    normalize_kernel<<<2 * ODIM, 256>>>(fw);

    cudaFuncSetAttribute(gemm_kernel, cudaFuncAttributeMaxDynamicSharedMemorySize, SMEM_TOTAL);
    gemm_kernel<<<BATCHN / BM, NTHR, SMEM_TOTAL>>>(x, y, fb, a0, a1, out);
}

// round 6
// speedup vs baseline: 1.4861x; 1.2926x over previous
#include <cuda_runtime.h>
#include <cstdint>

#define IND       1024
#define ODIM      128
#define BATCHN    65536
#define BM        64
#define KC        32                  // fp32 elems per K-chunk (128B row)
#define NITER     (IND / KC)          // 32
#define NS        2
#define NTHR      256

#define PANEL_F   (ODIM * KC)         // 4096 floats per W k-panel (16KB)

#define SM_MBAR     0                 // NS mbarriers (W TMA completion)
#define SM_COEF     256               // a0[128], a1[128], bias[128]
#define SM_STAGE    2048
#define XY_BYTES    8192              // 64 rows x 128B
#define W_BYTES     16384             // 128 rows x 128B
#define TO_X        0
#define TO_Y        8192
#define TO_W0       16384
#define TO_W1       32768
#define STAGE_BYTES 49152
#define W_TX        (2 * W_BYTES)     // expect_tx per stage (W0+W1)
#define SMEM_TOTAL  (SM_STAGE + NS * STAGE_BYTES)   // 100352
#define EXP         132               // exchange pitch (floats)

typedef uint32_t U32;

// W pre-packed per k-chunk, swizzle PRE-APPLIED so a linear bulk copy lands
// in smem with the exact layout the swizzled cp16 path produced.
__device__ float g_W0p[NITER * PANEL_F];
__device__ float g_W1p[NITER * PANEL_F];

// ---------------- PTX helpers ----------------

static __device__ __forceinline__ U32 s2u(const void* p) {
    U32 a;
    asm("{ .reg .u64 t; cvta.to.shared.u64 t, %1; cvt.u32.u64 %0, t; }" : "=r"(a) : "l"(p));
    return a;
}

static __device__ __forceinline__ void cp16(U32 dst, const void* src) {
    asm volatile("cp.async.cg.shared.global [%0], [%1], 16;" :: "r"(dst), "l"(src));
}
static __device__ __forceinline__ void cp_commit() {
    asm volatile("cp.async.commit_group;" ::: "memory");
}
template <int N> static __device__ __forceinline__ void cp_wait() {
    asm volatile("cp.async.wait_group %0;" :: "n"(N) : "memory");
}

static __device__ __forceinline__ void bulk_g2s(U32 dst, const void* src, U32 bytes, U32 mbar) {
    asm volatile("cp.async.bulk.shared::cluster.global.mbarrier::complete_tx::bytes "
                 "[%0], [%1], %2, [%3];"
                 :: "r"(dst), "l"(src), "r"(bytes), "r"(mbar) : "memory");
}

static __device__ __forceinline__ void mbar_init(U32 a, U32 cnt) {
    asm volatile("mbarrier.init.shared.b64 [%0], %1;" :: "r"(a), "r"(cnt) : "memory");
}
static __device__ __forceinline__ void mbar_expect(U32 a, U32 tx) {
    asm volatile("mbarrier.arrive.expect_tx.shared.b64 _, [%0], %1;" :: "r"(a), "r"(tx) : "memory");
}

#define MBAR_WAIT(addr, par) do {                                              \
    asm volatile("{\n\t.reg .pred P1;\n\t"                                     \
        "LAB_W_%=:\n\t"                                                        \
        "mbarrier.try_wait.parity.shared::cta.b64 P1, [%0], %1;\n\t"           \
        "@P1 bra.uni LAB_D_%=;\n\t"                                            \
        "bra.uni LAB_W_%=;\n\t"                                                \
        "LAB_D_%=:\n\t}"                                                       \
        :: "r"(addr), "r"(par) : "memory");                                    \
} while (0)

#define FENCE_PROXY() asm volatile("fence.proxy.async.shared::cta;" ::: "memory")

static __device__ __forceinline__ void ldsm4(U32& r0, U32& r1, U32& r2, U32& r3, U32 addr) {
    asm volatile("ldmatrix.sync.aligned.m8n8.x4.shared.b16 {%0,%1,%2,%3}, [%4];"
                 : "=r"(r0), "=r"(r1), "=r"(r2), "=r"(r3) : "r"(addr));
}

static __device__ __forceinline__ void mma8(float* c, U32 a0, U32 a1, U32 a2, U32 a3,
                                            U32 b0, U32 b1) {
    asm volatile("mma.sync.aligned.m16n8k8.row.col.f32.tf32.tf32.f32 "
                 "{%0,%1,%2,%3}, {%4,%5,%6,%7}, {%8,%9}, {%0,%1,%2,%3};"
                 : "+f"(c[0]), "+f"(c[1]), "+f"(c[2]), "+f"(c[3])
                 : "r"(a0), "r"(a1), "r"(a2), "r"(a3), "r"(b0), "r"(b1));
}

// ---------------- weight normalization + swizzled k-panel packing ----------------
// w' = (w - mean(w)) * rsqrt(sum((w-mean)^2))
// dst panel layout: [kchunk][row][col ^ ((row&7)<<2)] (float units)
__global__ void normalize_kernel(const float* __restrict__ w) {
    int row  = blockIdx.x & (ODIM - 1);
    int half = blockIdx.x >> 7;
    const float* src = w + (size_t)row * (2 * IND) + (size_t)half * IND;
    float* dst = half ? g_W1p : g_W0p;
    int t = threadIdx.x;  // 256 threads
    float v[4], s = 0.f, s2 = 0.f;
#pragma unroll
    for (int i = 0; i < 4; ++i) { v[i] = src[t + 256 * i]; s += v[i]; s2 += v[i] * v[i]; }
#pragma unroll
    for (int o = 16; o; o >>= 1) {
        s  += __shfl_xor_sync(~0u, s,  o);
        s2 += __shfl_xor_sync(~0u, s2, o);
    }
    __shared__ float sh[18];
    if ((t & 31) == 0) { sh[t >> 5] = s; sh[8 + (t >> 5)] = s2; }
    __syncthreads();
    if (t == 0) {
        float S = 0.f, S2 = 0.f;
#pragma unroll
        for (int i = 0; i < 8; ++i) { S += sh[i]; S2 += sh[8 + i]; }
        float mu = S * (1.f / IND);
        float ss = S2 - (float)IND * mu * mu;
        sh[16] = mu; sh[17] = rsqrtf(ss);
    }
    __syncthreads();
    float mu = sh[16], inv = sh[17];
#pragma unroll
    for (int i = 0; i < 4; ++i) {
        int k   = t + 256 * i;
        int kc  = k >> 5, col = k & 31;
        int sc  = col ^ ((row & 7) << 2);       // pre-applied 128B swizzle (float units)
        dst[(size_t)kc * PANEL_F + row * KC + sc] = (v[i] - mu) * inv;
    }
}

// ---------------- main fused GEMM ----------------
// 8 warps: warps 0-3: out0 = x*W0^T, warps 4-7: out1 = y*W1^T.
// Per-GEMM warp grid 2(m) x 2(n): warp tile 32x64. BM=64, 2 CTAs/SM.

static __device__ __forceinline__ void load_stage(U32 sb, int slot, int kchunk,
                                                  const float* x, const float* y, int m0) {
    const int tid = threadIdx.x;
    const U32 st = sb + SM_STAGE + slot * STAGE_BYTES;
    // x/y via cp.async: 1024 x 16B per stage, 4 per thread
    const int ch = tid & 7;          // 16B chunk within 128B row
    const int r0 = tid >> 3;         // base row 0..31
    const int kofs = kchunk * KC + ch * 4;
    const float* px = x + (size_t)(m0 + r0) * IND + kofs;
    const float* py = y + (size_t)(m0 + r0) * IND + kofs;
#pragma unroll
    for (int p = 0; p < 2; ++p) {
        const int row = r0 + 32 * p;
        const U32 c  = (U32)(ch * 16);
        const U32 so = (U32)(row * 128) + (c ^ (U32)((row & 7) << 4));
        cp16(st + TO_X + so, px + (size_t)(32 * p) * IND);
        cp16(st + TO_Y + so, py + (size_t)(32 * p) * IND);
    }
    // W via two 16KB bulk copies (pre-swizzled panels)
    if (tid == 0) {
        const U32 mb = sb + SM_MBAR + slot * 8;
        FENCE_PROXY();
        mbar_expect(mb, W_TX);
        bulk_g2s(st + TO_W0, g_W0p + (size_t)kchunk * PANEL_F, W_BYTES, mb);
        bulk_g2s(st + TO_W1, g_W1p + (size_t)kchunk * PANEL_F, W_BYTES, mb);
    }
}

__global__ void __launch_bounds__(NTHR, 2)
gemm_kernel(const float* __restrict__ x, const float* __restrict__ y,
            const float* __restrict__ fc_bias, const float* __restrict__ a0,
            const float* __restrict__ a1, float* __restrict__ out) {
    extern __shared__ char smem[];
    const U32 sb = s2u(smem);
    const int tid = threadIdx.x;
    const int wid = tid >> 5, lid = tid & 31;
    const int m0 = blockIdx.x * BM;

    if (tid == 0) {
#pragma unroll
        for (int s = 0; s < NS; ++s) mbar_init(sb + SM_MBAR + s * 8, 1);
    }
    if (tid < 128) {
        float* sc = (float*)(smem + SM_COEF);
        sc[tid] = a0[tid]; sc[128 + tid] = a1[tid]; sc[256 + tid] = fc_bias[tid];
    }
    __syncthreads();   // mbarriers initialized before any TMA

    // prologue: fill all NS stages
#pragma unroll
    for (int s = 0; s < NS; ++s) { load_stage(sb, s, s, x, y, m0); cp_commit(); }

    // warp role
    const int g1 = wid >> 2;             // 0: GEMM0 (x,W0), 1: GEMM1 (y,W1)
    const int wl = wid & 3;
    const int mw = wl & 1;               // m-half (32 rows)
    const int nw = wl >> 1;              // n-half (64 cols)

    const int sel  = lid >> 3;
    const int lrow = lid & 7;
    const int aRowL = (sel & 1) * 8 + lrow;
    const U32 aKb   = (U32)((sel >> 1) * 16);
    const int bRowL = sel * 8 + lrow;

    U32 aRowOff[2], aXor[2];
#pragma unroll
    for (int mt = 0; mt < 2; ++mt) {
        int r = mw * 32 + mt * 16 + aRowL;
        aRowOff[mt] = (U32)(r * 128);
        aXor[mt]    = (U32)((r & 7) << 4);
    }
    U32 bRowOff[2], bXor[2];
#pragma unroll
    for (int g = 0; g < 2; ++g) {
        int r = nw * 64 + g * 32 + bRowL;
        bRowOff[g] = (U32)(r * 128);
        bXor[g]    = (U32)((r & 7) << 4);
    }

    float acc[2][8][4];
#pragma unroll
    for (int mt = 0; mt < 2; ++mt)
#pragma unroll
        for (int nt = 0; nt < 8; ++nt)
#pragma unroll
            for (int q = 0; q < 4; ++q) acc[mt][nt][q] = 0.f;

    const U32 toA = g1 ? TO_Y : TO_X;
    const U32 toB = g1 ? TO_W1 : TO_W0;

    int phase0 = 0, phase1 = 0;
    for (int i = 0; i < NITER; ++i) {
        const int slot = i & 1;
        int ph = slot ? phase1 : phase0;
        MBAR_WAIT(sb + SM_MBAR + slot * 8, (U32)ph);     // W ready
        if (slot) phase1 ^= 1; else phase0 ^= 1;
        cp_wait<NS - 1>();                               // x/y ready
        __syncthreads();

        const U32 st = sb + SM_STAGE + (U32)(slot * STAGE_BYTES);
        const U32 abase = st + toA;
        const U32 bbase = st + toB;
#pragma unroll
        for (int ks = 0; ks < 4; ++ks) {       // 4 k8-steps per 32-float chunk
            const U32 kb = (U32)(ks * 32);
            U32 a[2][4];
#pragma unroll
            for (int mt = 0; mt < 2; ++mt)
                ldsm4(a[mt][0], a[mt][1], a[mt][2], a[mt][3],
                      abase + aRowOff[mt] + ((kb + aKb) ^ aXor[mt]));
            U32 b0[8], b1[8];
#pragma unroll
            for (int g = 0; g < 2; ++g) {
                ldsm4(b0[4 * g + 0], b0[4 * g + 1], b0[4 * g + 2], b0[4 * g + 3],
                      bbase + bRowOff[g] + ((kb + 0u)  ^ bXor[g]));
                ldsm4(b1[4 * g + 0], b1[4 * g + 1], b1[4 * g + 2], b1[4 * g + 3],
                      bbase + bRowOff[g] + ((kb + 16u) ^ bXor[g]));
            }
#pragma unroll
            for (int mt = 0; mt < 2; ++mt)
#pragma unroll
                for (int nt = 0; nt < 8; ++nt)
                    mma8(acc[mt][nt], a[mt][0], a[mt][1], a[mt][2], a[mt][3],
                         b0[nt], b1[nt]);
        }
        __syncthreads();                       // all warps done reading slot
        if (i + NS < NITER) load_stage(sb, slot, i + NS, x, y, m0);
        cp_commit();
    }
    __syncthreads();

    // ---------- epilogue ----------
    float* exch = (float*)(smem + SM_STAGE);   // reuse stage area: 64 x EXP fp32
    const float* sa0 = (const float*)(smem + SM_COEF);
    const float* sa1 = sa0 + 128;
    const float* sbs = sa0 + 256;

    const int rowb = mw * 32 + (lid >> 2);
    const int colb = nw * 64 + 2 * (lid & 3);

    if (!g1) {
#pragma unroll
        for (int mt = 0; mt < 2; ++mt) {
            const int rl = rowb + mt * 16;
#pragma unroll
            for (int nt = 0; nt < 8; ++nt) {
                const int c = colb + nt * 8;
                float2 v0 = make_float2(acc[mt][nt][0], acc[mt][nt][1]);
                float2 v1 = make_float2(acc[mt][nt][2], acc[mt][nt][3]);
                *(float2*)(out + (size_t)(m0 + rl)     * ODIM + c) = v0;
                *(float2*)(out + (size_t)(m0 + rl + 8) * ODIM + c) = v1;
                *(float2*)(exch + rl * EXP + c)       = v0;
                *(float2*)(exch + (rl + 8) * EXP + c) = v1;
            }
        }
    } else {
        float* o1 = out + (size_t)BATCHN * ODIM;
#pragma unroll
        for (int mt = 0; mt < 2; ++mt) {
            const int rl = rowb + mt * 16;
#pragma unroll
            for (int nt = 0; nt < 8; ++nt) {
                const int c = colb + nt * 8;
                *(float2*)(o1 + (size_t)(m0 + rl)     * ODIM + c) =
                    make_float2(acc[mt][nt][0], acc[mt][nt][1]);
                *(float2*)(o1 + (size_t)(m0 + rl + 8) * ODIM + c) =
                    make_float2(acc[mt][nt][2], acc[mt][nt][3]);
            }
        }
    }
    __syncthreads();

    if (g1) {
        float* o2 = out + 2 * (size_t)BATCHN * ODIM;
#pragma unroll
        for (int mt = 0; mt < 2; ++mt) {
            const int rl = rowb + mt * 16;
#pragma unroll
            for (int nt = 0; nt < 8; ++nt) {
                const int c = colb + nt * 8;
                float2 p0 = *(const float2*)(exch + rl * EXP + c);
                float2 p1 = *(const float2*)(exch + (rl + 8) * EXP + c);
                const float A0x = sa0[c], A0y = sa0[c + 1];
                const float A1x = sa1[c], A1y = sa1[c + 1];
                const float Bx  = sbs[c], By  = sbs[c + 1];
                float2 r0, r1;
                r0.x = p0.x * A0x + acc[mt][nt][0] * A1x + Bx;
                r0.y = p0.y * A0y + acc[mt][nt][1] * A1y + By;
                r1.x = p1.x * A0x + acc[mt][nt][2] * A1x + Bx;
                r1.y = p1.y * A0y + acc[mt][nt][3] * A1y + By;
                *(float2*)(o2 + (size_t)(m0 + rl)     * ODIM + c) = r0;
                *(float2*)(o2 + (size_t)(m0 + rl + 8) * ODIM + c) = r1;
            }
        }
    }
}

// ---------------- launch ----------------

extern "C" void kernel_launch(void* const* d_in, const int* in_sizes, int n_in,
                              void* d_out, int out_size) {
    const float* x  = (const float*)d_in[0];
    const float* y  = (const float*)d_in[1];
    const float* fw = (const float*)d_in[2];
    const float* fb = (const float*)d_in[3];
    const float* a0 = (const float*)d_in[4];
    const float* a1 = (const float*)d_in[5];
    float* out = (float*)d_out;

    normalize_kernel<<<2 * ODIM, 256>>>(fw);

    cudaFuncSetAttribute(gemm_kernel, cudaFuncAttributeMaxDynamicSharedMemorySize, SMEM_TOTAL);
    gemm_kernel<<<BATCHN / BM, NTHR, SMEM_TOTAL>>>(x, y, fb, a0, a1, out);
}